// round 14
// baseline (speedup 1.0000x reference)
#include <cuda_runtime.h>
#include <math.h>

constexpr int C   = 32;
constexpr int N_H = 40000, D_H = 16;
constexpr int N_O = 20000, D_O = 48;

constexpr int WPB   = 8;
constexpr int BLOCK = WPB * 32;          // 256 threads, warp = 1 atom
constexpr int NB_O  = N_O / WPB;         // 2500
constexpr int NB_H  = N_H / WPB;         // 5000
constexpr int NB    = NB_O + NB_H;       // 7500; bid%3==0 -> O else H

typedef unsigned long long u64;

// ---- packed f32x2 helpers (Blackwell FFMA2 path, PTX-only) ----
__device__ __forceinline__ u64 fma2(u64 a, u64 b, u64 c) {
    u64 d;
    asm("fma.rn.f32x2 %0, %1, %2, %3;" : "=l"(d) : "l"(a), "l"(b), "l"(c));
    return d;
}
__device__ __forceinline__ u64 add2(u64 a, u64 b) {
    u64 d;
    asm("add.rn.f32x2 %0, %1, %2;" : "=l"(d) : "l"(a), "l"(b));
    return d;
}
__device__ __forceinline__ u64 mul2(u64 a, u64 b) {
    u64 d;
    asm("mul.rn.f32x2 %0, %1, %2;" : "=l"(d) : "l"(a), "l"(b));
    return d;
}
__device__ __forceinline__ u64 pack2(float lo, float hi) {
    u64 d;
    asm("mov.b64 %0, {%1, %2};" : "=l"(d) : "r"(__float_as_uint(lo)), "r"(__float_as_uint(hi)));
    return d;
}
__device__ __forceinline__ void unpack2(u64 v, float& lo, float& hi) {
    unsigned int a, b;
    asm("mov.b64 {%0, %1}, %2;" : "=r"(a), "=r"(b) : "l"(v));
    lo = __uint_as_float(a);
    hi = __uint_as_float(b);
}

// Folded lower-triangular S, row i padded to a multiple of 4 floats (zeros).
__host__ __device__ constexpr int rowLen(int i) { return (i + 4) & ~3; }
__host__ __device__ constexpr int rowOff(int i) {
    int s = 0;
    for (int t = 0; t < i; t++) s += rowLen(t);
    return s;
}
template <int D>
__host__ __device__ constexpr int triTot() { return rowOff(D); }

constexpr int TRI_O_F = triTot<D_O>();        // 1248 floats
constexpr int TRI_H_F = triTot<D_H>();        // 160 floats
constexpr int TOT_F   = TRI_O_F + TRI_H_F;    // 1408 floats (5632 B)
constexpr int TOT_Q   = TOT_F / 4;            // 352 x 16B chunks
constexpr int BASE_O_Q = 0;
constexpr int BASE_H_Q = TRI_O_F / 4;         // 312

// Scratch (device global, written by prep kernel) and the constant-space copy.
// Even row-pairs read cS (constant port); odd row-pairs read g_sfold via
// warp-uniform __ldg (L1 port) — the S stream rides two independent pipes.
__device__ ulonglong2 g_sfold[TOT_Q];
__constant__ ulonglong2 cS[TOT_Q];

// Prep: thread i<48 folds O row i; thread 64+i (i<16) folds H row i.
__global__ void prepS(const float* __restrict__ S_H,
                      const float* __restrict__ S_O) {
    float* g = reinterpret_cast<float*>(g_sfold);
    const int t = threadIdx.x;
    if (t < D_O) {
        const int off = rowOff(t);
        for (int j = 0; j < t; j++) g[off + j] = 2.0f * S_O[t * D_O + j];
        g[off + t] = S_O[t * D_O + t];
        for (int j = t + 1; j < rowLen(t); j++) g[off + j] = 0.0f;
    } else if (t >= 64 && t - 64 < D_H) {
        const int i = t - 64;
        const int off = TRI_O_F + rowOff(i);
        for (int j = 0; j < i; j++) g[off + j] = 2.0f * S_H[i * D_H + j];
        g[off + i] = S_H[i * D_H + i];
        for (int j = i + 1; j < rowLen(i); j++) g[off + j] = 0.0f;
    }
}

// Warp = 1 atom, lane = channel; rows packed in pairs into u64.
// Even row-pairs: LDC.128 (constant port, floor 8/SMSP). Odd row-pairs:
// uniform LDG.128 from the tiny L1-resident global table. Each port carries
// half the S stream; both stay under the DRAM roofline.
template <int D, int BASEQ>
__device__ __forceinline__ void processAtom(const float* __restrict__ x,
                                            float* __restrict__ out,
                                            int baseRow, int lane) {
    constexpr int KP = D / 2;
    const float* xp = x + (size_t)baseRow * C + lane;

    u64 y2[KP];
#pragma unroll
    for (int k = 0; k < KP; k++) {
        float a = __ldg(xp + (2 * k + 0) * C);
        float b = __ldg(xp + (2 * k + 1) * C);
        y2[k] = pack2(a, b);
    }

    u64 accA = 0ull, accB = 0ull;
#pragma unroll
    for (int k = 0; k < KP; k++) {
        const int i0 = 2 * k;
        const int nc = k / 2 + 1;                    // 16B chunks per row
        const int q0 = BASEQ + (rowOff(i0) >> 2);    // compile-time constants
        const int q1 = BASEQ + (rowOff(i0 + 1) >> 2);
        const bool useC = (k & 1) == 0;              // compile-time after unroll

        // even row 2k
        u64 e0 = 0ull, e1 = 0ull;
#pragma unroll
        for (int jc = 0; jc < nc; jc++) {
            ulonglong2 a = useC ? cS[q0 + jc] : __ldg(&g_sfold[q0 + jc]);
            e0 = fma2(a.x, y2[2 * jc + 0], e0);
            e1 = fma2(a.y, y2[2 * jc + 1], e1);
        }
        float el, eh;
        unpack2(add2(e0, e1), el, eh);

        // odd row 2k+1
        u64 o0 = 0ull, o1 = 0ull;
#pragma unroll
        for (int jc = 0; jc < nc; jc++) {
            ulonglong2 b = useC ? cS[q1 + jc] : __ldg(&g_sfold[q1 + jc]);
            o0 = fma2(b.x, y2[2 * jc + 0], o0);
            o1 = fma2(b.y, y2[2 * jc + 1], o1);
        }
        float ol, oh;
        unpack2(add2(o0, o1), ol, oh);

        if (k & 1)
            accB = fma2(y2[k], pack2(el + eh, ol + oh), accB);
        else
            accA = fma2(y2[k], pack2(el + eh, ol + oh), accA);
    }

    float alo, ahi;
    unpack2(add2(accA, accB), alo, ahi);
    const float inv  = 1.0f / (sqrtf(alo + ahi) + 1e-6f);
    const u64   inv2 = pack2(inv, inv);

    float* op = out + (size_t)baseRow * C + lane;
#pragma unroll
    for (int k = 0; k < KP; k++) {
        u64 m = mul2(y2[k], inv2);
        float s0, s1;
        unpack2(m, s0, s1);
        op[(2 * k + 0) * C] = s0;
        op[(2 * k + 1) * C] = s1;
    }
}

// Fused: every 3rd block is an O block, the other two are H blocks (1:2 mix
// per SM). No shared memory, no fill, no block-level sync.
__global__ __launch_bounds__(BLOCK, 4) void l2norm_fused(
    const float* __restrict__ x,
    const int* __restrict__ idx_H, const int* __restrict__ idx_O,
    float* __restrict__ out) {
    const int warp = threadIdx.x >> 5;
    const int lane = threadIdx.x & 31;
    const int bid  = blockIdx.x;
    const int q    = bid / 3;
    const int r    = bid - 3 * q;

    if (r == 0) {
        const int atom = q * WPB + warp;
        const int baseRow = __ldg(idx_O + atom * D_O);
        processAtom<D_O, BASE_O_Q>(x, out, baseRow, lane);
    } else {
        const int atom = (2 * q + (r - 1)) * WPB + warp;
        const int baseRow = __ldg(idx_H + atom * D_H);
        processAtom<D_H, BASE_H_Q>(x, out, baseRow, lane);
    }
}

extern "C" void kernel_launch(void* const* d_in, const int* in_sizes, int n_in,
                              void* d_out, int out_size) {
    const float* x     = (const float*)d_in[0];
    const float* S_H   = (const float*)d_in[1];
    const float* S_O   = (const float*)d_in[2];
    const int*   idx_H = (const int*)d_in[3];
    const int*   idx_O = (const int*)d_in[4];
    float* out = (float*)d_out;

    // 1) fold S into device scratch, 2) D2D copy into constant bank,
    // 3) main kernel. All graph-capturable (kernel, memcpy node, kernel).
    prepS<<<1, 256>>>(S_H, S_O);

    void* scratchPtr = nullptr;
    cudaGetSymbolAddress(&scratchPtr, g_sfold);
    cudaMemcpyToSymbolAsync(cS, scratchPtr, sizeof(cS), 0,
                            cudaMemcpyDeviceToDevice, 0);

    l2norm_fused<<<NB, BLOCK>>>(x, idx_H, idx_O, out);
}

// round 15
// speedup vs baseline: 1.1943x; 1.1943x over previous
#include <cuda_runtime.h>
#include <math.h>

constexpr int C   = 32;
constexpr int N_H = 40000, D_H = 16;
constexpr int N_O = 20000, D_O = 48;

constexpr int WPB   = 8;
constexpr int BLOCK = WPB * 32;          // 256 threads, warp = 1 atom
constexpr int NB_O  = N_O / WPB;         // 2500
constexpr int NB_H  = N_H / WPB;         // 5000
constexpr int NB    = NB_O + NB_H;       // 7500; bid%3==0 -> O else H

typedef unsigned long long u64;

// ---- packed f32x2 helpers (Blackwell FFMA2 path, PTX-only) ----
__device__ __forceinline__ u64 fma2(u64 a, u64 b, u64 c) {
    u64 d;
    asm("fma.rn.f32x2 %0, %1, %2, %3;" : "=l"(d) : "l"(a), "l"(b), "l"(c));
    return d;
}
__device__ __forceinline__ u64 add2(u64 a, u64 b) {
    u64 d;
    asm("add.rn.f32x2 %0, %1, %2;" : "=l"(d) : "l"(a), "l"(b));
    return d;
}
__device__ __forceinline__ u64 mul2(u64 a, u64 b) {
    u64 d;
    asm("mul.rn.f32x2 %0, %1, %2;" : "=l"(d) : "l"(a), "l"(b));
    return d;
}
__device__ __forceinline__ u64 pack2(float lo, float hi) {
    u64 d;
    asm("mov.b64 %0, {%1, %2};" : "=l"(d) : "r"(__float_as_uint(lo)), "r"(__float_as_uint(hi)));
    return d;
}
__device__ __forceinline__ void unpack2(u64 v, float& lo, float& hi) {
    unsigned int a, b;
    asm("mov.b64 {%0, %1}, %2;" : "=r"(a), "=r"(b) : "l"(v));
    lo = __uint_as_float(a);
    hi = __uint_as_float(b);
}
__device__ __forceinline__ void cpAsync16(unsigned int saddr, const void* gptr) {
    asm volatile("cp.async.cg.shared.global [%0], [%1], 16;" :: "r"(saddr), "l"(gptr));
}

// Folded lower-triangular S, row i padded to a multiple of 4 floats (zeros).
__host__ __device__ constexpr int rowLen(int i) { return (i + 4) & ~3; }
__host__ __device__ constexpr int rowOff(int i) {
    int s = 0;
    for (int t = 0; t < i; t++) s += rowLen(t);
    return s;
}
template <int D>
__host__ __device__ constexpr int triTot() { return rowOff(D); }

constexpr int TRI_O_F = triTot<D_O>();        // 1248 floats
constexpr int TRI_H_F = triTot<D_H>();        // 160 floats
constexpr int TOT_F   = TRI_O_F + TRI_H_F;    // 1408 floats (5632 B)
constexpr int TOT_Q   = TOT_F / 4;            // 352 x 16B chunks
constexpr int BASE_O_Q = 0;
constexpr int BASE_H_Q = TRI_O_F / 4;         // 312

// Folded table: device scratch (prep), constant copy (even row-pairs),
// per-block smem copy (odd row-pairs) -> S stream split across two ports.
__device__ __align__(16) ulonglong2 g_sfold[TOT_Q];
__constant__ ulonglong2 cS[TOT_Q];

// Prep: thread i<48 folds O row i; thread 64+i (i<16) folds H row i.
__global__ void prepS(const float* __restrict__ S_H,
                      const float* __restrict__ S_O) {
    float* g = reinterpret_cast<float*>(g_sfold);
    const int t = threadIdx.x;
    if (t < D_O) {
        const int off = rowOff(t);
        for (int j = 0; j < t; j++) g[off + j] = 2.0f * S_O[t * D_O + j];
        g[off + t] = S_O[t * D_O + t];
        for (int j = t + 1; j < rowLen(t); j++) g[off + j] = 0.0f;
    } else if (t >= 64 && t - 64 < D_H) {
        const int i = t - 64;
        const int off = TRI_O_F + rowOff(i);
        for (int j = 0; j < i; j++) g[off + j] = 2.0f * S_H[i * D_H + j];
        g[off + i] = S_H[i * D_H + i];
        for (int j = i + 1; j < rowLen(i); j++) g[off + j] = 0.0f;
    }
}

// Warp = 1 atom, lane = channel; rows packed in pairs into u64.
// Even row-pairs read S via LDC (constant port, immediate addresses); odd
// row-pairs via LDS (shared crossbar, immediate offsets from one base reg).
// Sync for the cp.async table copy happens AFTER the y loads are issued, so
// the copy latency hides entirely under the idx->y global-load chain.
template <int D, int BASEQ>
__device__ __forceinline__ void processAtom(const float* __restrict__ x,
                                            float* __restrict__ out,
                                            const ulonglong2* __restrict__ Sp,
                                            int baseRow, int lane) {
    constexpr int KP = D / 2;
    const float* xp = x + (size_t)baseRow * C + lane;

    u64 y2[KP];
#pragma unroll
    for (int k = 0; k < KP; k++) {
        float a = __ldg(xp + (2 * k + 0) * C);
        float b = __ldg(xp + (2 * k + 1) * C);
        y2[k] = pack2(a, b);
    }

    // Table copy must be complete before the k-loop reads Sp.
    asm volatile("cp.async.wait_group 0;" ::: "memory");
    __syncthreads();

    u64 accA = 0ull, accB = 0ull;
#pragma unroll
    for (int k = 0; k < KP; k++) {
        const int i0 = 2 * k;
        const int nc = k / 2 + 1;                    // 16B chunks per row
        const int q0 = BASEQ + (rowOff(i0) >> 2);    // compile-time constants
        const int q1 = BASEQ + (rowOff(i0 + 1) >> 2);
        const bool useC = (k & 1) == 0;              // compile-time after unroll

        // even row 2k
        u64 e0 = 0ull, e1 = 0ull;
#pragma unroll
        for (int jc = 0; jc < nc; jc++) {
            ulonglong2 a = useC ? cS[q0 + jc] : Sp[q0 + jc];
            e0 = fma2(a.x, y2[2 * jc + 0], e0);
            e1 = fma2(a.y, y2[2 * jc + 1], e1);
        }
        float el, eh;
        unpack2(add2(e0, e1), el, eh);

        // odd row 2k+1
        u64 o0 = 0ull, o1 = 0ull;
#pragma unroll
        for (int jc = 0; jc < nc; jc++) {
            ulonglong2 b = useC ? cS[q1 + jc] : Sp[q1 + jc];
            o0 = fma2(b.x, y2[2 * jc + 0], o0);
            o1 = fma2(b.y, y2[2 * jc + 1], o1);
        }
        float ol, oh;
        unpack2(add2(o0, o1), ol, oh);

        if (k & 1)
            accB = fma2(y2[k], pack2(el + eh, ol + oh), accB);
        else
            accA = fma2(y2[k], pack2(el + eh, ol + oh), accA);
    }

    float alo, ahi;
    unpack2(add2(accA, accB), alo, ahi);
    const float inv  = 1.0f / (sqrtf(alo + ahi) + 1e-6f);
    const u64   inv2 = pack2(inv, inv);

    float* op = out + (size_t)baseRow * C + lane;
#pragma unroll
    for (int k = 0; k < KP; k++) {
        u64 m = mul2(y2[k], inv2);
        float s0, s1;
        unpack2(m, s0, s1);
        op[(2 * k + 0) * C] = s0;
        op[(2 * k + 1) * C] = s1;
    }
}

// Fused: every 3rd block is an O block, the other two are H blocks (1:2 mix
// per SM). The r==0 / r!=0 branch is block-uniform, so the __syncthreads
// inside processAtom is reached by all threads.
__global__ __launch_bounds__(BLOCK, 4) void l2norm_fused(
    const float* __restrict__ x,
    const int* __restrict__ idx_H, const int* __restrict__ idx_O,
    float* __restrict__ out) {
    __shared__ __align__(16) ulonglong2 Sp[TOT_Q];

    // Fire the table copy FIRST (cp.async: no dest registers), no wait yet.
    {
        unsigned int sbase = (unsigned int)__cvta_generic_to_shared(Sp);
        const int t = threadIdx.x;
        cpAsync16(sbase + t * 16, g_sfold + t);
        if (t + BLOCK < TOT_Q)
            cpAsync16(sbase + (t + BLOCK) * 16, g_sfold + t + BLOCK);
        asm volatile("cp.async.commit_group;" ::: "memory");
    }

    const int warp = threadIdx.x >> 5;
    const int lane = threadIdx.x & 31;
    const int bid  = blockIdx.x;
    const int q    = bid / 3;
    const int r    = bid - 3 * q;

    if (r == 0) {
        const int atom = q * WPB + warp;
        const int baseRow = __ldg(idx_O + atom * D_O);
        processAtom<D_O, BASE_O_Q>(x, out, Sp, baseRow, lane);
    } else {
        const int atom = (2 * q + (r - 1)) * WPB + warp;
        const int baseRow = __ldg(idx_H + atom * D_H);
        processAtom<D_H, BASE_H_Q>(x, out, Sp, baseRow, lane);
    }
}

extern "C" void kernel_launch(void* const* d_in, const int* in_sizes, int n_in,
                              void* d_out, int out_size) {
    const float* x     = (const float*)d_in[0];
    const float* S_H   = (const float*)d_in[1];
    const float* S_O   = (const float*)d_in[2];
    const int*   idx_H = (const int*)d_in[3];
    const int*   idx_O = (const int*)d_in[4];
    float* out = (float*)d_out;

    // 1) fold S into device scratch, 2) D2D copy into constant bank,
    // 3) main kernel. All graph-capturable (kernel, memcpy node, kernel).
    prepS<<<1, 256>>>(S_H, S_O);

    void* scratchPtr = nullptr;
    cudaGetSymbolAddress(&scratchPtr, g_sfold);
    cudaMemcpyToSymbolAsync(cS, scratchPtr, sizeof(cS), 0,
                            cudaMemcpyDeviceToDevice, 0);

    l2norm_fused<<<NB, BLOCK>>>(x, idx_H, idx_O, out);
}

// round 16
// speedup vs baseline: 1.3977x; 1.1703x over previous
#include <cuda_runtime.h>
#include <math.h>

constexpr int C   = 32;
constexpr int N_H = 40000, D_H = 16;
constexpr int N_O = 20000, D_O = 48;

constexpr int WPB   = 8;
constexpr int BLOCK = WPB * 32;          // 256 threads
constexpr int NB_O  = N_O / WPB;         // 2500 (warp = 1 O atom)
constexpr int NB_H2 = N_H / (2 * WPB);   // 2500 (warp = 2 H atoms)
constexpr int NB    = NB_O + NB_H2;      // 5000; bid even -> O, odd -> H2

typedef unsigned long long u64;

// ---- packed f32x2 helpers (Blackwell FFMA2 path, PTX-only) ----
__device__ __forceinline__ u64 fma2(u64 a, u64 b, u64 c) {
    u64 d;
    asm("fma.rn.f32x2 %0, %1, %2, %3;" : "=l"(d) : "l"(a), "l"(b), "l"(c));
    return d;
}
__device__ __forceinline__ u64 add2(u64 a, u64 b) {
    u64 d;
    asm("add.rn.f32x2 %0, %1, %2;" : "=l"(d) : "l"(a), "l"(b));
    return d;
}
__device__ __forceinline__ u64 mul2(u64 a, u64 b) {
    u64 d;
    asm("mul.rn.f32x2 %0, %1, %2;" : "=l"(d) : "l"(a), "l"(b));
    return d;
}
__device__ __forceinline__ u64 pack2(float lo, float hi) {
    u64 d;
    asm("mov.b64 %0, {%1, %2};" : "=l"(d) : "r"(__float_as_uint(lo)), "r"(__float_as_uint(hi)));
    return d;
}
__device__ __forceinline__ void unpack2(u64 v, float& lo, float& hi) {
    unsigned int a, b;
    asm("mov.b64 {%0, %1}, %2;" : "=r"(a), "=r"(b) : "l"(v));
    lo = __uint_as_float(a);
    hi = __uint_as_float(b);
}

// Folded lower-triangular S, row i padded to a multiple of 4 floats (zeros).
__host__ __device__ constexpr int rowLen(int i) { return (i + 4) & ~3; }
__host__ __device__ constexpr int rowOff(int i) {
    int s = 0;
    for (int t = 0; t < i; t++) s += rowLen(t);
    return s;
}
template <int D>
__host__ __device__ constexpr int triTot() { return rowOff(D); }

constexpr int TRI_O_F = triTot<D_O>();        // 1248 floats
constexpr int TRI_H_F = triTot<D_H>();        // 160 floats
constexpr int TOT_F   = TRI_O_F + TRI_H_F;    // 1408 floats (5632 B)
constexpr int TOT_Q   = TOT_F / 4;            // 352 x 16B chunks
constexpr int BASE_O_Q = 0;
constexpr int BASE_H_Q = TRI_O_F / 4;         // 312

// Scratch (device global, written by prep kernel) and the constant-space copy.
__device__ __align__(16) ulonglong2 g_sfold[TOT_Q];
__constant__ ulonglong2 cS[TOT_Q];

// Prep: thread i<48 folds O row i; thread 64+i (i<16) folds H row i.
__global__ void prepS(const float* __restrict__ S_H,
                      const float* __restrict__ S_O) {
    float* g = reinterpret_cast<float*>(g_sfold);
    const int t = threadIdx.x;
    if (t < D_O) {
        const int off = rowOff(t);
        for (int j = 0; j < t; j++) g[off + j] = 2.0f * S_O[t * D_O + j];
        g[off + t] = S_O[t * D_O + t];
        for (int j = t + 1; j < rowLen(t); j++) g[off + j] = 0.0f;
    } else if (t >= 64 && t - 64 < D_H) {
        const int i = t - 64;
        const int off = TRI_O_F + rowOff(i);
        for (int j = 0; j < i; j++) g[off + j] = 2.0f * S_H[i * D_H + j];
        g[off + i] = S_H[i * D_H + i];
        for (int j = i + 1; j < rowLen(i); j++) g[off + j] = 0.0f;
    }
}

// O path: warp = 1 atom, lane = channel, rows packed in pairs into u64.
// S via constant port (LDC, compile-time immediate addresses). Unchanged R12.
template <int D, int BASEQ>
__device__ __forceinline__ void processAtom(const float* __restrict__ x,
                                            float* __restrict__ out,
                                            int baseRow, int lane) {
    constexpr int KP = D / 2;
    const float* xp = x + (size_t)baseRow * C + lane;

    u64 y2[KP];
#pragma unroll
    for (int k = 0; k < KP; k++) {
        float a = __ldg(xp + (2 * k + 0) * C);
        float b = __ldg(xp + (2 * k + 1) * C);
        y2[k] = pack2(a, b);
    }

    u64 accA = 0ull, accB = 0ull;
#pragma unroll
    for (int k = 0; k < KP; k++) {
        const int i0 = 2 * k;
        const int nc = k / 2 + 1;
        const int q0 = BASEQ + (rowOff(i0) >> 2);
        const int q1 = BASEQ + (rowOff(i0 + 1) >> 2);

        u64 e0 = 0ull, e1 = 0ull;
#pragma unroll
        for (int jc = 0; jc < nc; jc++) {
            ulonglong2 a = cS[q0 + jc];
            e0 = fma2(a.x, y2[2 * jc + 0], e0);
            e1 = fma2(a.y, y2[2 * jc + 1], e1);
        }
        float el, eh;
        unpack2(add2(e0, e1), el, eh);

        u64 o0 = 0ull, o1 = 0ull;
#pragma unroll
        for (int jc = 0; jc < nc; jc++) {
            ulonglong2 b = cS[q1 + jc];
            o0 = fma2(b.x, y2[2 * jc + 0], o0);
            o1 = fma2(b.y, y2[2 * jc + 1], o1);
        }
        float ol, oh;
        unpack2(add2(o0, o1), ol, oh);

        if (k & 1)
            accB = fma2(y2[k], pack2(el + eh, ol + oh), accB);
        else
            accA = fma2(y2[k], pack2(el + eh, ol + oh), accA);
    }

    float alo, ahi;
    unpack2(add2(accA, accB), alo, ahi);
    const float inv  = 1.0f / (sqrtf(alo + ahi) + 1e-6f);
    const u64   inv2 = pack2(inv, inv);

    float* op = out + (size_t)baseRow * C + lane;
#pragma unroll
    for (int k = 0; k < KP; k++) {
        u64 m = mul2(y2[k], inv2);
        float s0, s1;
        unpack2(m, s0, s1);
        op[(2 * k + 0) * C] = s0;
        op[(2 * k + 1) * C] = s1;
    }
}

// H path: warp = 2 atoms. 32 front-batched LDGs (2x MLP vs 1-atom H) and each
// S chunk is loaded ONCE and reused for both atoms (halves H's LDC count).
__device__ __forceinline__ void processAtomH2(const float* __restrict__ x,
                                              float* __restrict__ out,
                                              int rowA, int rowB, int lane) {
    constexpr int KP = D_H / 2;  // 8
    const float* xa = x + (size_t)rowA * C + lane;
    const float* xb = x + (size_t)rowB * C + lane;

    u64 ya[KP], yb[KP];
#pragma unroll
    for (int k = 0; k < KP; k++) {
        float a0 = __ldg(xa + (2 * k + 0) * C);
        float a1 = __ldg(xa + (2 * k + 1) * C);
        float b0 = __ldg(xb + (2 * k + 0) * C);
        float b1 = __ldg(xb + (2 * k + 1) * C);
        ya[k] = pack2(a0, a1);
        yb[k] = pack2(b0, b1);
    }

    u64 accA = 0ull, accB = 0ull;
#pragma unroll
    for (int k = 0; k < KP; k++) {
        const int i0 = 2 * k;
        const int nc = k / 2 + 1;
        const int q0 = BASE_H_Q + (rowOff(i0) >> 2);
        const int q1 = BASE_H_Q + (rowOff(i0 + 1) >> 2);

        // even row 2k — one chunk load feeds both atoms
        u64 eA = 0ull, eB = 0ull;
#pragma unroll
        for (int jc = 0; jc < nc; jc++) {
            ulonglong2 s = cS[q0 + jc];
            eA = fma2(s.x, ya[2 * jc + 0], eA);
            eA = fma2(s.y, ya[2 * jc + 1], eA);
            eB = fma2(s.x, yb[2 * jc + 0], eB);
            eB = fma2(s.y, yb[2 * jc + 1], eB);
        }
        float eAl, eAh, eBl, eBh;
        unpack2(eA, eAl, eAh);
        unpack2(eB, eBl, eBh);

        // odd row 2k+1
        u64 oA = 0ull, oB = 0ull;
#pragma unroll
        for (int jc = 0; jc < nc; jc++) {
            ulonglong2 s = cS[q1 + jc];
            oA = fma2(s.x, ya[2 * jc + 0], oA);
            oA = fma2(s.y, ya[2 * jc + 1], oA);
            oB = fma2(s.x, yb[2 * jc + 0], oB);
            oB = fma2(s.y, yb[2 * jc + 1], oB);
        }
        float oAl, oAh, oBl, oBh;
        unpack2(oA, oAl, oAh);
        unpack2(oB, oBl, oBh);

        accA = fma2(ya[k], pack2(eAl + eAh, oAl + oAh), accA);
        accB = fma2(yb[k], pack2(eBl + eBh, oBl + oBh), accB);
    }

    float aAl, aAh, aBl, aBh;
    unpack2(accA, aAl, aAh);
    unpack2(accB, aBl, aBh);
    const float invA = 1.0f / (sqrtf(aAl + aAh) + 1e-6f);
    const float invB = 1.0f / (sqrtf(aBl + aBh) + 1e-6f);
    const u64 invA2 = pack2(invA, invA);
    const u64 invB2 = pack2(invB, invB);

    float* oa = out + (size_t)rowA * C + lane;
    float* ob = out + (size_t)rowB * C + lane;
#pragma unroll
    for (int k = 0; k < KP; k++) {
        u64 ma = mul2(ya[k], invA2);
        u64 mb = mul2(yb[k], invB2);
        float s0, s1, t0, t1;
        unpack2(ma, s0, s1);
        unpack2(mb, t0, t1);
        oa[(2 * k + 0) * C] = s0;
        oa[(2 * k + 1) * C] = s1;
        ob[(2 * k + 0) * C] = t0;
        ob[(2 * k + 1) * C] = t1;
    }
}

// Fused: even blocks O (1 atom/warp), odd blocks H2 (2 atoms/warp) — 1:1 mix
// per SM; identical total work, fewer+fatter H tasks with doubled MLP.
__global__ __launch_bounds__(BLOCK, 4) void l2norm_fused(
    const float* __restrict__ x,
    const int* __restrict__ idx_H, const int* __restrict__ idx_O,
    float* __restrict__ out) {
    const int warp = threadIdx.x >> 5;
    const int lane = threadIdx.x & 31;
    const int bid  = blockIdx.x;
    const int q    = bid >> 1;

    if ((bid & 1) == 0) {
        const int atom = q * WPB + warp;
        const int baseRow = __ldg(idx_O + atom * D_O);
        processAtom<D_O, BASE_O_Q>(x, out, baseRow, lane);
    } else {
        const int pair = q * WPB + warp;
        const int rowA = __ldg(idx_H + (2 * pair + 0) * D_H);
        const int rowB = __ldg(idx_H + (2 * pair + 1) * D_H);
        processAtomH2(x, out, rowA, rowB, lane);
    }
}

extern "C" void kernel_launch(void* const* d_in, const int* in_sizes, int n_in,
                              void* d_out, int out_size) {
    const float* x     = (const float*)d_in[0];
    const float* S_H   = (const float*)d_in[1];
    const float* S_O   = (const float*)d_in[2];
    const int*   idx_H = (const int*)d_in[3];
    const int*   idx_O = (const int*)d_in[4];
    float* out = (float*)d_out;

    prepS<<<1, 256>>>(S_H, S_O);

    void* scratchPtr = nullptr;
    cudaGetSymbolAddress(&scratchPtr, g_sfold);
    cudaMemcpyToSymbolAsync(cS, scratchPtr, sizeof(cS), 0,
                            cudaMemcpyDeviceToDevice, 0);

    l2norm_fused<<<NB, BLOCK>>>(x, idx_H, idx_O, out);
}

// round 17
// speedup vs baseline: 1.4776x; 1.0572x over previous
#include <cuda_runtime.h>
#include <math.h>

constexpr int C   = 32;
constexpr int N_H = 40000, D_H = 16;
constexpr int N_O = 20000, D_O = 48;

constexpr int WPB   = 8;
constexpr int BLOCK = WPB * 32;          // 256 threads
constexpr int NB_O  = N_O / WPB;         // 2500 (warp = 1 O atom)
constexpr int NB_H2 = N_H / (2 * WPB);   // 2500 (warp = 2 H atoms)
constexpr int NB    = NB_O + NB_H2;      // 5000; bid even -> O, odd -> H2

typedef unsigned long long u64;

// ---- packed f32x2 helpers (Blackwell FFMA2 path, PTX-only) ----
__device__ __forceinline__ u64 fma2(u64 a, u64 b, u64 c) {
    u64 d;
    asm("fma.rn.f32x2 %0, %1, %2, %3;" : "=l"(d) : "l"(a), "l"(b), "l"(c));
    return d;
}
__device__ __forceinline__ u64 add2(u64 a, u64 b) {
    u64 d;
    asm("add.rn.f32x2 %0, %1, %2;" : "=l"(d) : "l"(a), "l"(b));
    return d;
}
__device__ __forceinline__ u64 mul2(u64 a, u64 b) {
    u64 d;
    asm("mul.rn.f32x2 %0, %1, %2;" : "=l"(d) : "l"(a), "l"(b));
    return d;
}
__device__ __forceinline__ u64 pack2(float lo, float hi) {
    u64 d;
    asm("mov.b64 %0, {%1, %2};" : "=l"(d) : "r"(__float_as_uint(lo)), "r"(__float_as_uint(hi)));
    return d;
}
__device__ __forceinline__ void unpack2(u64 v, float& lo, float& hi) {
    unsigned int a, b;
    asm("mov.b64 {%0, %1}, %2;" : "=r"(a), "=r"(b) : "l"(v));
    lo = __uint_as_float(a);
    hi = __uint_as_float(b);
}

// Folded lower-triangular S, row i padded to a multiple of 4 floats (zeros).
__host__ __device__ constexpr int rowLen(int i) { return (i + 4) & ~3; }
__host__ __device__ constexpr int rowOff(int i) {
    int s = 0;
    for (int t = 0; t < i; t++) s += rowLen(t);
    return s;
}
template <int D>
__host__ __device__ constexpr int triTot() { return rowOff(D); }

constexpr int TRI_O_F = triTot<D_O>();        // 1248 floats
constexpr int TRI_H_F = triTot<D_H>();        // 160 floats
constexpr int TOT_F   = TRI_O_F + TRI_H_F;    // 1408 floats (5632 B)
constexpr int TOT_Q   = TOT_F / 4;            // 352 x 16B chunks
constexpr int BASE_O_Q = 0;
constexpr int BASE_H_Q = TRI_O_F / 4;         // 312

// Constant bank read by the main kernel via LDC. Populated DIRECTLY by the
// prep kernel (constant memory is normal device memory; the per-SM constant
// cache is invalidated at kernel-launch boundaries, so a prior kernel's
// stores are exactly as visible as a cudaMemcpyToSymbol of the same bytes).
__constant__ ulonglong2 cS[TOT_Q];

// Prep: thread i<48 folds O row i; thread 64+i (i<16) folds H row i.
// Writes straight into the constant bank through its device address.
__global__ void prepS(float* __restrict__ dst,
                      const float* __restrict__ S_H,
                      const float* __restrict__ S_O) {
    const int t = threadIdx.x;
    if (t < D_O) {
        const int off = rowOff(t);
        for (int j = 0; j < t; j++) dst[off + j] = 2.0f * S_O[t * D_O + j];
        dst[off + t] = S_O[t * D_O + t];
        for (int j = t + 1; j < rowLen(t); j++) dst[off + j] = 0.0f;
    } else if (t >= 64 && t - 64 < D_H) {
        const int i = t - 64;
        const int off = TRI_O_F + rowOff(i);
        for (int j = 0; j < i; j++) dst[off + j] = 2.0f * S_H[i * D_H + j];
        dst[off + i] = S_H[i * D_H + i];
        for (int j = i + 1; j < rowLen(i); j++) dst[off + j] = 0.0f;
    }
}

// O path: warp = 1 atom, lane = channel, rows packed in pairs into u64.
// S via constant port (LDC, compile-time immediate addresses). x/out use
// streaming (.cs evict-first) hints: strictly read-once / write-once.
template <int D, int BASEQ>
__device__ __forceinline__ void processAtom(const float* __restrict__ x,
                                            float* __restrict__ out,
                                            int baseRow, int lane) {
    constexpr int KP = D / 2;
    const float* xp = x + (size_t)baseRow * C + lane;

    u64 y2[KP];
#pragma unroll
    for (int k = 0; k < KP; k++) {
        float a = __ldcs(xp + (2 * k + 0) * C);
        float b = __ldcs(xp + (2 * k + 1) * C);
        y2[k] = pack2(a, b);
    }

    u64 accA = 0ull, accB = 0ull;
#pragma unroll
    for (int k = 0; k < KP; k++) {
        const int i0 = 2 * k;
        const int nc = k / 2 + 1;
        const int q0 = BASEQ + (rowOff(i0) >> 2);
        const int q1 = BASEQ + (rowOff(i0 + 1) >> 2);

        u64 e0 = 0ull, e1 = 0ull;
#pragma unroll
        for (int jc = 0; jc < nc; jc++) {
            ulonglong2 a = cS[q0 + jc];
            e0 = fma2(a.x, y2[2 * jc + 0], e0);
            e1 = fma2(a.y, y2[2 * jc + 1], e1);
        }
        float el, eh;
        unpack2(add2(e0, e1), el, eh);

        u64 o0 = 0ull, o1 = 0ull;
#pragma unroll
        for (int jc = 0; jc < nc; jc++) {
            ulonglong2 b = cS[q1 + jc];
            o0 = fma2(b.x, y2[2 * jc + 0], o0);
            o1 = fma2(b.y, y2[2 * jc + 1], o1);
        }
        float ol, oh;
        unpack2(add2(o0, o1), ol, oh);

        if (k & 1)
            accB = fma2(y2[k], pack2(el + eh, ol + oh), accB);
        else
            accA = fma2(y2[k], pack2(el + eh, ol + oh), accA);
    }

    float alo, ahi;
    unpack2(add2(accA, accB), alo, ahi);
    const float inv  = 1.0f / (sqrtf(alo + ahi) + 1e-6f);
    const u64   inv2 = pack2(inv, inv);

    float* op = out + (size_t)baseRow * C + lane;
#pragma unroll
    for (int k = 0; k < KP; k++) {
        u64 m = mul2(y2[k], inv2);
        float s0, s1;
        unpack2(m, s0, s1);
        __stcs(op + (2 * k + 0) * C, s0);
        __stcs(op + (2 * k + 1) * C, s1);
    }
}

// H path: warp = 2 atoms. 32 front-batched LDGs (2x MLP) and each S chunk is
// loaded ONCE and reused for both atoms (halves H's LDC count).
__device__ __forceinline__ void processAtomH2(const float* __restrict__ x,
                                              float* __restrict__ out,
                                              int rowA, int rowB, int lane) {
    constexpr int KP = D_H / 2;  // 8
    const float* xa = x + (size_t)rowA * C + lane;
    const float* xb = x + (size_t)rowB * C + lane;

    u64 ya[KP], yb[KP];
#pragma unroll
    for (int k = 0; k < KP; k++) {
        float a0 = __ldcs(xa + (2 * k + 0) * C);
        float a1 = __ldcs(xa + (2 * k + 1) * C);
        float b0 = __ldcs(xb + (2 * k + 0) * C);
        float b1 = __ldcs(xb + (2 * k + 1) * C);
        ya[k] = pack2(a0, a1);
        yb[k] = pack2(b0, b1);
    }

    u64 accA = 0ull, accB = 0ull;
#pragma unroll
    for (int k = 0; k < KP; k++) {
        const int i0 = 2 * k;
        const int nc = k / 2 + 1;
        const int q0 = BASE_H_Q + (rowOff(i0) >> 2);
        const int q1 = BASE_H_Q + (rowOff(i0 + 1) >> 2);

        // even row 2k — one chunk load feeds both atoms
        u64 eA = 0ull, eB = 0ull;
#pragma unroll
        for (int jc = 0; jc < nc; jc++) {
            ulonglong2 s = cS[q0 + jc];
            eA = fma2(s.x, ya[2 * jc + 0], eA);
            eA = fma2(s.y, ya[2 * jc + 1], eA);
            eB = fma2(s.x, yb[2 * jc + 0], eB);
            eB = fma2(s.y, yb[2 * jc + 1], eB);
        }
        float eAl, eAh, eBl, eBh;
        unpack2(eA, eAl, eAh);
        unpack2(eB, eBl, eBh);

        // odd row 2k+1
        u64 oA = 0ull, oB = 0ull;
#pragma unroll
        for (int jc = 0; jc < nc; jc++) {
            ulonglong2 s = cS[q1 + jc];
            oA = fma2(s.x, ya[2 * jc + 0], oA);
            oA = fma2(s.y, ya[2 * jc + 1], oA);
            oB = fma2(s.x, yb[2 * jc + 0], oB);
            oB = fma2(s.y, yb[2 * jc + 1], oB);
        }
        float oAl, oAh, oBl, oBh;
        unpack2(oA, oAl, oAh);
        unpack2(oB, oBl, oBh);

        accA = fma2(ya[k], pack2(eAl + eAh, oAl + oAh), accA);
        accB = fma2(yb[k], pack2(eBl + eBh, oBl + oBh), accB);
    }

    float aAl, aAh, aBl, aBh;
    unpack2(accA, aAl, aAh);
    unpack2(accB, aBl, aBh);
    const float invA = 1.0f / (sqrtf(aAl + aAh) + 1e-6f);
    const float invB = 1.0f / (sqrtf(aBl + aBh) + 1e-6f);
    const u64 invA2 = pack2(invA, invA);
    const u64 invB2 = pack2(invB, invB);

    float* oa = out + (size_t)rowA * C + lane;
    float* ob = out + (size_t)rowB * C + lane;
#pragma unroll
    for (int k = 0; k < KP; k++) {
        u64 ma = mul2(ya[k], invA2);
        u64 mb = mul2(yb[k], invB2);
        float s0, s1, t0, t1;
        unpack2(ma, s0, s1);
        unpack2(mb, t0, t1);
        __stcs(oa + (2 * k + 0) * C, s0);
        __stcs(oa + (2 * k + 1) * C, s1);
        __stcs(ob + (2 * k + 0) * C, t0);
        __stcs(ob + (2 * k + 1) * C, t1);
    }
}

// Fused: even blocks O (1 atom/warp), odd blocks H2 (2 atoms/warp) — 1:1 mix
// per SM; identical total work, fewer+fatter H tasks with doubled MLP.
__global__ __launch_bounds__(BLOCK, 4) void l2norm_fused(
    const float* __restrict__ x,
    const int* __restrict__ idx_H, const int* __restrict__ idx_O,
    float* __restrict__ out) {
    const int warp = threadIdx.x >> 5;
    const int lane = threadIdx.x & 31;
    const int bid  = blockIdx.x;
    const int q    = bid >> 1;

    if ((bid & 1) == 0) {
        const int atom = q * WPB + warp;
        const int baseRow = __ldg(idx_O + atom * D_O);
        processAtom<D_O, BASE_O_Q>(x, out, baseRow, lane);
    } else {
        const int pair = q * WPB + warp;
        const int rowA = __ldg(idx_H + (2 * pair + 0) * D_H);
        const int rowB = __ldg(idx_H + (2 * pair + 1) * D_H);
        processAtomH2(x, out, rowA, rowB, lane);
    }
}

extern "C" void kernel_launch(void* const* d_in, const int* in_sizes, int n_in,
                              void* d_out, int out_size) {
    const float* x     = (const float*)d_in[0];
    const float* S_H   = (const float*)d_in[1];
    const float* S_O   = (const float*)d_in[2];
    const int*   idx_H = (const int*)d_in[3];
    const int*   idx_O = (const int*)d_in[4];
    float* out = (float*)d_out;

    // Prep writes the folded table straight into the constant bank: the
    // 3-node chain (prep -> memcpyToSymbol -> main) becomes 2 nodes.
    void* cSaddr = nullptr;
    cudaGetSymbolAddress(&cSaddr, cS);
    prepS<<<1, 256>>>((float*)cSaddr, S_H, S_O);

    l2norm_fused<<<NB, BLOCK>>>(x, idx_H, idx_O, out);
}